// round 11
// baseline (speedup 1.0000x reference)
#include <cuda_runtime.h>
#include <cuda_bf16.h>
#include <stdint.h>

#define BB 2
#define CC 128
#define NN 4096
#define SCALE 0.08838834764831845f   // 128^-0.5

// ---------------- scratch (no allocations allowed) -------------------------
__device__ float2         g_stats[BB*32];      // per (b,group): mean, rstd
__device__ uint8_t        g_Qf[BB*NN*CC];      // [b][n][c] e4m3
__device__ uint8_t        g_Kf[BB*NN*CC];      // [b][n][c] e4m3
__device__ __nv_bfloat16  g_Vh[BB*NN*CC];      // [b][n][c] bf16
__device__ __nv_bfloat16  g_Opb[BB*2*NN*CC];   // partial O, [b][sp][n][c] bf16
__device__ float          g_l [BB*2*NN];       // partial softmax sums

extern __shared__ char dynsmem[];

// ---------------- PTX helpers (baseline-safe: sm_80/sm_89-era) -------------
__device__ __forceinline__ uint32_t smem_u32(const void* p) {
  uint32_t a;
  asm("{ .reg .u64 t; cvta.to.shared.u64 t, %1; cvt.u32.u64 %0, t; }"
      : "=r"(a) : "l"(p));
  return a;
}
__device__ __forceinline__ void ldsm_x4(uint32_t& r0, uint32_t& r1,
                                        uint32_t& r2, uint32_t& r3, uint32_t a) {
  asm volatile("ldmatrix.sync.aligned.m8n8.x4.shared.b16 {%0,%1,%2,%3}, [%4];"
               : "=r"(r0), "=r"(r1), "=r"(r2), "=r"(r3) : "r"(a));
}
__device__ __forceinline__ void ldsm_x4_t(uint32_t& r0, uint32_t& r1,
                                          uint32_t& r2, uint32_t& r3, uint32_t a) {
  asm volatile("ldmatrix.sync.aligned.m8n8.x4.trans.shared.b16 {%0,%1,%2,%3}, [%4];"
               : "=r"(r0), "=r"(r1), "=r"(r2), "=r"(r3) : "r"(a));
}
__device__ __forceinline__ void mma_bf16(float* d, const uint32_t* a,
                                         const uint32_t* b, const float* c) {
  asm volatile(
    "mma.sync.aligned.m16n8k16.row.col.f32.bf16.bf16.f32 "
    "{%0,%1,%2,%3}, {%4,%5,%6,%7}, {%8,%9}, {%10,%11,%12,%13};"
    : "=f"(d[0]), "=f"(d[1]), "=f"(d[2]), "=f"(d[3])
    : "r"(a[0]), "r"(a[1]), "r"(a[2]), "r"(a[3]),
      "r"(b[0]), "r"(b[1]),
      "f"(c[0]), "f"(c[1]), "f"(c[2]), "f"(c[3]));
}
__device__ __forceinline__ void mma_fp8(float* d, const uint32_t* a,
                                        const uint32_t* b, const float* c) {
  asm volatile(
    "mma.sync.aligned.m16n8k32.row.col.f32.e4m3.e4m3.f32 "
    "{%0,%1,%2,%3}, {%4,%5,%6,%7}, {%8,%9}, {%10,%11,%12,%13};"
    : "=f"(d[0]), "=f"(d[1]), "=f"(d[2]), "=f"(d[3])
    : "r"(a[0]), "r"(a[1]), "r"(a[2]), "r"(a[3]),
      "r"(b[0]), "r"(b[1]),
      "f"(c[0]), "f"(c[1]), "f"(c[2]), "f"(c[3]));
}
__device__ __forceinline__ uint32_t pk2(float lo, float hi) {
  uint32_t r;
  asm("cvt.rn.bf16x2.f32 %0, %1, %2;" : "=r"(r) : "f"(hi), "f"(lo));
  return r;
}
__device__ __forceinline__ uint16_t pke4(float lo, float hi) {
  uint16_t r;
  asm("cvt.rn.satfinite.e4m3x2.f32 %0, %1, %2;" : "=h"(r) : "f"(hi), "f"(lo));
  return r;
}
__device__ __forceinline__ void cpa16(uint32_t dst, const void* src) {
  asm volatile("cp.async.cg.shared.global [%0], [%1], 16;" :: "r"(dst), "l"(src));
}
__device__ __forceinline__ void cp_commit() {
  asm volatile("cp.async.commit_group;" ::: "memory");
}
template <int N> __device__ __forceinline__ void cp_wait() {
  asm volatile("cp.async.wait_group %0;" :: "n"(N) : "memory");
}

// ---------------------------------------------------------------------------
// Kernel 1: GroupNorm stats. 64 blocks = (b, group), 1024 threads.
// ---------------------------------------------------------------------------
__global__ __launch_bounds__(1024) void gn_stats_kernel(const float* __restrict__ x) {
  int b = blockIdx.x >> 5;
  int g = blockIdx.x & 31;
  const float4* xp = (const float4*)(x + ((size_t)b*CC + g*4)*NN);
  float s = 0.f, s2 = 0.f;
  for (int i = threadIdx.x; i < 4096; i += 1024) {
    float4 v = xp[i];
    s  += v.x + v.y + v.z + v.w;
    s2 += v.x*v.x + v.y*v.y + v.z*v.z + v.w*v.w;
  }
  #pragma unroll
  for (int o = 16; o; o >>= 1) {
    s  += __shfl_xor_sync(0xffffffffu, s, o);
    s2 += __shfl_xor_sync(0xffffffffu, s2, o);
  }
  __shared__ float rs[32], rs2[32];
  int wid = threadIdx.x >> 5;
  if ((threadIdx.x & 31) == 0) { rs[wid] = s; rs2[wid] = s2; }
  __syncthreads();
  if (threadIdx.x == 0) {
    float S = 0.f, S2 = 0.f;
    #pragma unroll
    for (int i = 0; i < 32; i++) { S += rs[i]; S2 += rs2[i]; }
    float mean = S * (1.f/16384.f);
    float var  = S2 * (1.f/16384.f) - mean*mean;
    g_stats[blockIdx.x] = make_float2(mean, rsqrtf(var + 1e-5f));
  }
}

// ---------------------------------------------------------------------------
// Kernel 2: fused GN-apply + Q/K/V GEMM, HMMA. grid = BB*32, 256 thr.
// Q,K emitted as e4m3 [n][c]; V as bf16 [n][c].
// ---------------------------------------------------------------------------
__global__ __launch_bounds__(256) void qkv_kernel(
    const float* __restrict__ x,
    const float* __restrict__ gamma, const float* __restrict__ beta,
    const float* __restrict__ wq, const float* __restrict__ bq,
    const float* __restrict__ wk, const float* __restrict__ bk,
    const float* __restrict__ wv, const float* __restrict__ bv) {
  char* smem = dynsmem;
  uint32_t sb = smem_u32(smem);
  uint32_t sbW = sb + 32768;

  int b  = blockIdx.x >> 5;
  int n0 = (blockIdx.x & 31) << 7;
  int t  = threadIdx.x;
  int w  = t >> 5;
  int lane = t & 31;

  // stage normalized H tile [c][n0..n0+128) -> bf16, swizzled
  for (int i = t; i < 2048; i += 256) {
    int c = i >> 4, j8 = i & 15;
    float2 st = g_stats[b*32 + (c >> 2)];
    float ga = gamma[c] * st.y;
    float be = beta[c] - st.x * ga;
    const float4* hp = (const float4*)(x + ((size_t)b*CC + c)*NN + n0 + j8*8);
    float4 f0 = hp[0], f1 = hp[1];
    uint4 o;
    o.x = pk2(f0.x*ga+be, f0.y*ga+be); o.y = pk2(f0.z*ga+be, f0.w*ga+be);
    o.z = pk2(f1.x*ga+be, f1.y*ga+be); o.w = pk2(f1.z*ga+be, f1.w*ga+be);
    *(uint4*)(smem + c*256 + ((j8 ^ (c & 7)) << 4)) = o;
  }
  __syncthreads();

  // A-fragments of H^T (rows n, k = c) via trans ldmatrix
  uint32_t qa[8][4];
  {
    int krow_lo = ((lane >> 4) << 3) + (lane & 7);
    int mcol    = w*16 + (((lane >> 3) & 1) << 3);
    int mch     = mcol >> 3;
    #pragma unroll
    for (int ks = 0; ks < 8; ks++) {
      int krow = ks*16 + krow_lo;
      uint32_t a = sb + krow*256 + ((mch ^ (krow & 7)) << 4);
      ldsm_x4_t(qa[ks][0], qa[ks][1], qa[ks][2], qa[ks][3], a);
    }
  }

  const float* Wp[3] = {wq, wk, wv};
  const float* Bp[3] = {bq, bk, bv};

  int rl   = lane & 7;
  int hf   = (lane >> 3) & 1;
  int nsel = (lane >> 4) & 1;
  int n_r  = n0 + w*16 + (lane >> 2);

  for (int m = 0; m < 3; m++) {
    __syncthreads();
    const float* wsrc = Wp[m];
    for (int i = t; i < 2048; i += 256) {
      int co = i >> 4, j8 = i & 15;
      const float4* pw = (const float4*)(wsrc + co*CC + j8*8);
      float4 f0 = pw[0], f1 = pw[1];
      uint4 o;
      o.x = pk2(f0.x, f0.y); o.y = pk2(f0.z, f0.w);
      o.z = pk2(f1.x, f1.y); o.w = pk2(f1.z, f1.w);
      *(uint4*)(smem + 32768 + co*256 + ((j8 ^ (co & 7)) << 4)) = o;
    }
    __syncthreads();

    const float* bias = Bp[m];
    #pragma unroll
    for (int nb = 0; nb < 16; nb += 2) {
      float a0[4] = {0.f,0.f,0.f,0.f};
      float a1[4] = {0.f,0.f,0.f,0.f};
      #pragma unroll
      for (int ks = 0; ks < 8; ks++) {
        uint32_t bb[4];
        uint32_t a = sbW + ((nb + nsel)*8 + rl)*256 + (((2*ks + hf) ^ rl) << 4);
        ldsm_x4(bb[0], bb[1], bb[2], bb[3], a);
        mma_bf16(a0, qa[ks], bb,     a0);
        mma_bf16(a1, qa[ks], bb + 2, a1);
      }
      #pragma unroll
      for (int u = 0; u < 2; u++) {
        float* ac = u ? a1 : a0;
        int co0 = (nb + u)*8 + (lane & 3)*2;
        float b0 = bias[co0], b1 = bias[co0 + 1];
        if (m < 2) {
          uint8_t* out = (m == 0 ? g_Qf : g_Kf) + (size_t)b*NN*CC;
          *(uint16_t*)(out + (size_t)n_r*CC + co0)     = pke4(ac[0]+b0, ac[1]+b1);
          *(uint16_t*)(out + (size_t)(n_r+8)*CC + co0) = pke4(ac[2]+b0, ac[3]+b1);
        } else {
          __nv_bfloat16* out = g_Vh + (size_t)b*NN*CC;
          *(uint32_t*)(out + (size_t)n_r*CC + co0)     = pk2(ac[0]+b0, ac[1]+b1);
          *(uint32_t*)(out + (size_t)(n_r+8)*CC + co0) = pk2(ac[2]+b0, ac[3]+b1);
        }
      }
    }
  }
}

// ---------------------------------------------------------------------------
// Kernel 3: flash attention — fp8 S-phase (m16n8k32 e4m3), bf16 PV.
// grid = 128 CTAs, 256 thr. Double-buffered cp.async K/V.
// Buffer layout per stage (24KB): K fp8 [64key][128B] @0, V bf16 @8192.
// Q fp8 [128q][128B] staged in buf1.
// ---------------------------------------------------------------------------
__global__ __launch_bounds__(256) void attn_kernel() {
  char* smem = dynsmem;
  uint32_t sb = smem_u32(smem);
  const uint32_t BUF = 24576;

  int t    = threadIdx.x;
  int w    = t >> 5;
  int lane = t & 31;
  int bid  = blockIdx.x;
  int b    = bid >> 6;
  int qt   = (bid >> 1) & 31;
  int sp   = bid & 1;
  int q0   = qt << 7;
  int kb0  = sp << 11;

  const uint8_t*       Kf = g_Qf - g_Qf + g_Kf + (size_t)b*NN*CC;  // g_Kf base
  const __nv_bfloat16* Vg = g_Vh + (size_t)b*NN*CC;

  // ---- stage Q tile (fp8, swizzled 128B rows) into buf1 ----
  for (int i = t; i < 1024; i += 256) {
    int row = i >> 3, cb = i & 7;
    *(uint4*)(smem + BUF + row*128 + ((cb ^ (row & 7)) << 4)) =
        *(const uint4*)(g_Qf + ((size_t)b*NN + q0 + row)*CC + cb*16);
  }
  __syncthreads();

  // prefetch tile 0 into buf0 (K fp8: 512 chunks; V bf16: 1024 chunks)
  {
    int kb = kb0;
    for (int i = t; i < 1536; i += 256) {
      if (i < 512) {
        int row = i >> 3, cb = i & 7;
        cpa16(sb + row*128 + ((cb ^ (row & 7)) << 4),
              Kf + ((size_t)(kb + row))*CC + cb*16);
      } else {
        int j = i - 512;
        int row = j >> 4, cb = j & 15;
        cpa16(sb + 8192 + row*256 + ((cb ^ (row & 7)) << 4),
              Vg + ((size_t)(kb + row))*CC + cb*8);
      }
    }
    cp_commit();
  }

  // Q a-frags (fp8 m16k32): 4 k-steps x 4 regs
  uint32_t qa[4][4];
  {
    int row = w*16 + (lane & 15);
    int kc  = (lane >> 4) & 1;
    #pragma unroll
    for (int ks = 0; ks < 4; ks++) {
      int chunk = 2*ks + kc;
      uint32_t a = sb + BUF + row*128 + ((chunk ^ (row & 7)) << 4);
      ldsm_x4(qa[ks][0], qa[ks][1], qa[ks][2], qa[ks][3], a);
    }
  }
  __syncthreads();   // Q frags in regs; buf1 free

  // prefetch tile 1 into buf1
  {
    int kb = kb0 + 64;
    for (int i = t; i < 1536; i += 256) {
      if (i < 512) {
        int row = i >> 3, cb = i & 7;
        cpa16(sb + BUF + row*128 + ((cb ^ (row & 7)) << 4),
              Kf + ((size_t)(kb + row))*CC + cb*16);
      } else {
        int j = i - 512;
        int row = j >> 4, cb = j & 15;
        cpa16(sb + BUF + 8192 + row*256 + ((cb ^ (row & 7)) << 4),
              Vg + ((size_t)(kb + row))*CC + cb*8);
      }
    }
    cp_commit();
  }

  int nsel = (lane >> 4) & 1;
  // fp8 B-frag lane addressing for S: key = (nb + lane>>4)*8 + (lane&7),
  // chunk = 2j + ((lane>>3)&1)
  int skey_lo = (lane & 7);
  int sgrp    = (lane >> 4) & 1;
  int schf    = (lane >> 3) & 1;

  float oacc[16][4];
  #pragma unroll
  for (int nb = 0; nb < 16; nb++)
    { oacc[nb][0]=0.f; oacc[nb][1]=0.f; oacc[nb][2]=0.f; oacc[nb][3]=0.f; }
  float l0 = 0.f, l1 = 0.f;

  for (int kt = 0; kt < 32; kt++) {
    if (kt < 31) cp_wait<1>(); else cp_wait<0>();
    __syncthreads();

    uint32_t Ks = sb + (uint32_t)(kt & 1)*BUF;
    uint32_t Vs = Ks + 8192;

    // ---- S = Q K^T  (fp8, nb pairs via x4 across key-groups) ----
    float sacc[8][4];
    #pragma unroll
    for (int nb = 0; nb < 8; nb += 2) {
      float* s0 = sacc[nb];
      float* s1 = sacc[nb+1];
      s0[0]=0.f; s0[1]=0.f; s0[2]=0.f; s0[3]=0.f;
      s1[0]=0.f; s1[1]=0.f; s1[2]=0.f; s1[3]=0.f;
      #pragma unroll
      for (int j = 0; j < 4; j++) {
        int key   = (nb + sgrp)*8 + skey_lo;
        int chunk = 2*j + schf;
        uint32_t bb[4];
        uint32_t a = Ks + key*128 + ((chunk ^ (key & 7)) << 4);
        ldsm_x4(bb[0], bb[1], bb[2], bb[3], a);
        mma_fp8(s0, qa[j], bb,     s0);
        mma_fp8(s1, qa[j], bb + 2, s1);
      }
    }

    // ---- exp + row sums ----
    float rs0 = 0.f, rs1 = 0.f;
    #pragma unroll
    for (int nb = 0; nb < 8; nb++) {
      float p0 = __expf(fminf(sacc[nb][0]*SCALE, 80.f));
      float p1 = __expf(fminf(sacc[nb][1]*SCALE, 80.f));
      float p2 = __expf(fminf(sacc[nb][2]*SCALE, 80.f));
      float p3 = __expf(fminf(sacc[nb][3]*SCALE, 80.f));
      sacc[nb][0]=p0; sacc[nb][1]=p1; sacc[nb][2]=p2; sacc[nb][3]=p3;
      rs0 += p0 + p1;
      rs1 += p2 + p3;
    }
    rs0 += __shfl_xor_sync(0xffffffffu, rs0, 1);
    rs0 += __shfl_xor_sync(0xffffffffu, rs0, 2);
    rs1 += __shfl_xor_sync(0xffffffffu, rs1, 1);
    rs1 += __shfl_xor_sync(0xffffffffu, rs1, 2);
    l0 += rs0;
    l1 += rs1;

    // ---- O += P V  (bf16, trans B loads from V[key][ch]) ----
    #pragma unroll
    for (int ks = 0; ks < 4; ks++) {
      uint32_t pa[4];
      pa[0] = pk2(sacc[2*ks][0],   sacc[2*ks][1]);
      pa[1] = pk2(sacc[2*ks][2],   sacc[2*ks][3]);
      pa[2] = pk2(sacc[2*ks+1][0], sacc[2*ks+1][1]);
      pa[3] = pk2(sacc[2*ks+1][2], sacc[2*ks+1][3]);
      int vrow = ks*16 + (lane & 15);
      uint32_t abase = Vs + vrow*256;
      uint32_t sw = (uint32_t)(vrow & 7) << 4;
      #pragma unroll
      for (int nb = 0; nb < 16; nb += 2) {
        uint32_t bb[4];
        uint32_t a = abase + (((uint32_t)((nb + nsel) << 4)) ^ sw);
        ldsm_x4_t(bb[0], bb[1], bb[2], bb[3], a);
        mma_bf16(oacc[nb],   pa, bb,     oacc[nb]);
        mma_bf16(oacc[nb+1], pa, bb + 2, oacc[nb+1]);
      }
    }

    __syncthreads();
    if (kt + 2 < 32) {
      int kb = kb0 + ((kt + 2) << 6);
      uint32_t base = sb + (uint32_t)(kt & 1)*BUF;
      for (int i = t; i < 1536; i += 256) {
        if (i < 512) {
          int row = i >> 3, cb = i & 7;
          cpa16(base + row*128 + ((cb ^ (row & 7)) << 4),
                Kf + ((size_t)(kb + row))*CC + cb*16);
        } else {
          int j = i - 512;
          int row = j >> 4, cb = j & 15;
          cpa16(base + 8192 + row*256 + ((cb ^ (row & 7)) << 4),
                Vg + ((size_t)(kb + row))*CC + cb*8);
        }
      }
      cp_commit();
    }
  }

  // ---- epilogue: bf16 partial O and fp32 l ----
  int r0 = q0 + w*16 + (lane >> 2);
  __nv_bfloat16* Og = g_Opb + ((size_t)(b*2 + sp)*NN + r0)*CC;
  int col = (lane & 3)*2;
  #pragma unroll
  for (int nb = 0; nb < 16; nb++) {
    *(uint32_t*)(Og + nb*8 + col)                = pk2(oacc[nb][0], oacc[nb][1]);
    *(uint32_t*)(Og + (size_t)8*CC + nb*8 + col) = pk2(oacc[nb][2], oacc[nb][3]);
  }
  if ((lane & 3) == 0) {
    g_l[(size_t)(b*2 + sp)*NN + r0]     = l0;
    g_l[(size_t)(b*2 + sp)*NN + r0 + 8] = l1;
  }
}

// ---------------------------------------------------------------------------
// Kernel 4: combine + projection + bias + residual, HMMA.
// Stages A-tile from the two split-KV partials on the fly.
// ---------------------------------------------------------------------------
__global__ __launch_bounds__(256) void proj_kernel(
    const float* __restrict__ x,
    const float* __restrict__ wp,
    const float* __restrict__ bp,
    float* __restrict__ outp) {
  char* smem = dynsmem;
  uint32_t sb = smem_u32(smem);
  uint32_t sbW = sb + 32768;
  float* Ot = (float*)smem;

  int b  = blockIdx.x >> 5;
  int n0 = (blockIdx.x & 31) << 7;
  int t  = threadIdx.x;
  int w  = t >> 5;
  int lane = t & 31;

  // stage A tile = (O_sp0 + O_sp1) / (l0 + l1), bf16, swizzled
  for (int i = t; i < 2048; i += 256) {
    int row = i >> 4, cb = i & 15;
    int n = n0 + row;
    float inv = 1.f / (g_l[(size_t)(b*2)*NN + n] + g_l[(size_t)(b*2+1)*NN + n]);
    uint4 ua = *(const uint4*)(g_Opb + ((size_t)(b*2)*NN + n)*CC + cb*8);
    uint4 uc = *(const uint4*)(g_Opb + ((size_t)(b*2+1)*NN + n)*CC + cb*8);
    const __nv_bfloat162* pa = (const __nv_bfloat162*)&ua;
    const __nv_bfloat162* pc = (const __nv_bfloat162*)&uc;
    uint4 o;
    uint32_t* po = (uint32_t*)&o;
    #pragma unroll
    for (int j = 0; j < 4; j++) {
      float2 fa = __bfloat1622float2(pa[j]);
      float2 fc = __bfloat1622float2(pc[j]);
      po[j] = pk2((fa.x + fc.x)*inv, (fa.y + fc.y)*inv);
    }
    *(uint4*)(smem + row*256 + ((cb ^ (row & 7)) << 4)) = o;
  }
  // stage wp fp32 -> bf16
  for (int i = t; i < 2048; i += 256) {
    int co = i >> 4, j8 = i & 15;
    const float4* pw = (const float4*)(wp + co*CC + j8*8);
    float4 f0 = pw[0], f1 = pw[1];
    uint4 o;
    o.x = pk2(f0.x, f0.y); o.y = pk2(f0.z, f0.w);
    o.z = pk2(f1.x, f1.y); o.w = pk2(f1.z, f1.w);
    *(uint4*)(smem + 32768 + co*256 + ((j8 ^ (co & 7)) << 4)) = o;
  }
  __syncthreads();

  uint32_t qa[8][4];
  {
    int row = w*16 + (lane & 15);
    int kc  = (lane >> 4) & 1;
    #pragma unroll
    for (int ks = 0; ks < 8; ks++) {
      uint32_t a = sb + row*256 + (((2*ks + kc) ^ (row & 7)) << 4);
      ldsm_x4(qa[ks][0], qa[ks][1], qa[ks][2], qa[ks][3], a);
    }
  }

  int rl   = lane & 7;
  int hf   = (lane >> 3) & 1;
  int nsel = (lane >> 4) & 1;

  float acc[16][4];
  #pragma unroll
  for (int nb = 0; nb < 16; nb += 2) {
    float* a0 = acc[nb];
    float* a1 = acc[nb+1];
    a0[0]=0.f; a0[1]=0.f; a0[2]=0.f; a0[3]=0.f;
    a1[0]=0.f; a1[1]=0.f; a1[2]=0.f; a1[3]=0.f;
    #pragma unroll
    for (int ks = 0; ks < 8; ks++) {
      uint32_t bb[4];
      uint32_t a = sbW + ((nb + nsel)*8 + rl)*256 + (((2*ks + hf) ^ rl) << 4);
      ldsm_x4(bb[0], bb[1], bb[2], bb[3], a);
      mma_bf16(a0, qa[ks], bb,     a0);
      mma_bf16(a1, qa[ks], bb + 2, a1);
    }
  }
  __syncthreads();   // reuse smem as Ot[128co][132]

  int nl = w*16 + (lane >> 2);
  #pragma unroll
  for (int nb = 0; nb < 16; nb++) {
    int co0 = nb*8 + (lane & 3)*2;
    Ot[co0*132 + nl]           = acc[nb][0];
    Ot[(co0 + 1)*132 + nl]     = acc[nb][1];
    Ot[co0*132 + nl + 8]       = acc[nb][2];
    Ot[(co0 + 1)*132 + nl + 8] = acc[nb][3];
  }
  __syncthreads();

  for (int i = t; i < 4096; i += 256) {
    int co = i >> 5, q = i & 31;
    float bias = bp[co];
    size_t base = (size_t)b*CC*NN + (size_t)co*NN + n0 + q*4;
    float4 xv = *(const float4*)&x[base];
    float4 hv = *(float4*)&Ot[co*132 + q*4];
    float4 o;
    o.x = xv.x + hv.x + bias;
    o.y = xv.y + hv.y + bias;
    o.z = xv.z + hv.z + bias;
    o.w = xv.w + hv.w + bias;
    *(float4*)&outp[base] = o;
  }
}

// ---------------------------------------------------------------------------
extern "C" void kernel_launch(void* const* d_in, const int* in_sizes, int n_in,
                              void* d_out, int out_size) {
  (void)in_sizes; (void)n_in; (void)out_size;
  const float* x    = (const float*)d_in[0];
  const float* gn_w = (const float*)d_in[1];
  const float* gn_b = (const float*)d_in[2];
  const float* wq   = (const float*)d_in[3];
  const float* bq   = (const float*)d_in[4];
  const float* wk   = (const float*)d_in[5];
  const float* bk   = (const float*)d_in[6];
  const float* wv   = (const float*)d_in[7];
  const float* bv   = (const float*)d_in[8];
  const float* wp   = (const float*)d_in[9];
  const float* bp   = (const float*)d_in[10];
  float* out = (float*)d_out;

  const int QKV_SMEM  = 65536;
  const int ATTN_SMEM = 49152;       // 2 x (8KB K fp8 + 16KB V bf16)
  const int PROJ_SMEM = 128*132*4;   // 67584
  cudaFuncSetAttribute(qkv_kernel,  cudaFuncAttributeMaxDynamicSharedMemorySize, QKV_SMEM);
  cudaFuncSetAttribute(attn_kernel, cudaFuncAttributeMaxDynamicSharedMemorySize, ATTN_SMEM);
  cudaFuncSetAttribute(proj_kernel, cudaFuncAttributeMaxDynamicSharedMemorySize, PROJ_SMEM);

  gn_stats_kernel<<<64, 1024>>>(x);
  qkv_kernel<<<64, 256, QKV_SMEM>>>(x, gn_w, gn_b, wq, bq, wk, bk, wv, bv);
  attn_kernel<<<128, 256, ATTN_SMEM>>>();
  proj_kernel<<<64, 256, PROJ_SMEM>>>(x, wp, bp, out);
}

// round 12
// speedup vs baseline: 1.1786x; 1.1786x over previous
#include <cuda_runtime.h>
#include <cuda_bf16.h>
#include <stdint.h>

#define BB 2
#define CC 128
#define NN 4096
#define SCALE 0.08838834764831845f   // 128^-0.5

// ---------------- scratch (no allocations allowed) -------------------------
__device__ float2         g_stats[BB*32];      // per (b,group): mean, rstd
__device__ __nv_bfloat16  g_Qh[BB*NN*CC];      // [b][n][c] bf16
__device__ __nv_bfloat16  g_Kh[BB*NN*CC];      // [b][n][c] bf16
__device__ __nv_bfloat16  g_Vh[BB*NN*CC];      // [b][n][c] bf16
__device__ __nv_bfloat16  g_Opb[BB*2*NN*CC];   // partial O, [b][sp][n][c] bf16
__device__ float          g_l [BB*2*NN];       // partial softmax sums

extern __shared__ char dynsmem[];

// ---------------- PTX helpers (baseline-safe, sm_80-era) -------------------
__device__ __forceinline__ uint32_t smem_u32(const void* p) {
  uint32_t a;
  asm("{ .reg .u64 t; cvta.to.shared.u64 t, %1; cvt.u32.u64 %0, t; }"
      : "=r"(a) : "l"(p));
  return a;
}
__device__ __forceinline__ void ldsm_x4(uint32_t& r0, uint32_t& r1,
                                        uint32_t& r2, uint32_t& r3, uint32_t a) {
  asm volatile("ldmatrix.sync.aligned.m8n8.x4.shared.b16 {%0,%1,%2,%3}, [%4];"
               : "=r"(r0), "=r"(r1), "=r"(r2), "=r"(r3) : "r"(a));
}
__device__ __forceinline__ void ldsm_x4_t(uint32_t& r0, uint32_t& r1,
                                          uint32_t& r2, uint32_t& r3, uint32_t a) {
  asm volatile("ldmatrix.sync.aligned.m8n8.x4.trans.shared.b16 {%0,%1,%2,%3}, [%4];"
               : "=r"(r0), "=r"(r1), "=r"(r2), "=r"(r3) : "r"(a));
}
__device__ __forceinline__ void mma_bf16(float* d, const uint32_t* a,
                                         const uint32_t* b, const float* c) {
  asm volatile(
    "mma.sync.aligned.m16n8k16.row.col.f32.bf16.bf16.f32 "
    "{%0,%1,%2,%3}, {%4,%5,%6,%7}, {%8,%9}, {%10,%11,%12,%13};"
    : "=f"(d[0]), "=f"(d[1]), "=f"(d[2]), "=f"(d[3])
    : "r"(a[0]), "r"(a[1]), "r"(a[2]), "r"(a[3]),
      "r"(b[0]), "r"(b[1]),
      "f"(c[0]), "f"(c[1]), "f"(c[2]), "f"(c[3]));
}
__device__ __forceinline__ uint32_t pk2(float lo, float hi) {
  uint32_t r;
  asm("cvt.rn.bf16x2.f32 %0, %1, %2;" : "=r"(r) : "f"(hi), "f"(lo));
  return r;
}
__device__ __forceinline__ void cpa16(uint32_t dst, const void* src) {
  asm volatile("cp.async.cg.shared.global [%0], [%1], 16;" :: "r"(dst), "l"(src));
}
__device__ __forceinline__ void cp_commit() {
  asm volatile("cp.async.commit_group;" ::: "memory");
}
template <int N> __device__ __forceinline__ void cp_wait() {
  asm volatile("cp.async.wait_group %0;" :: "n"(N) : "memory");
}

// ---------------------------------------------------------------------------
// Kernel 1: GroupNorm stats. 64 blocks = (b, group), 1024 threads.
// ---------------------------------------------------------------------------
__global__ __launch_bounds__(1024) void gn_stats_kernel(const float* __restrict__ x) {
  int b = blockIdx.x >> 5;
  int g = blockIdx.x & 31;
  const float4* xp = (const float4*)(x + ((size_t)b*CC + g*4)*NN);
  float s = 0.f, s2 = 0.f;
  for (int i = threadIdx.x; i < 4096; i += 1024) {
    float4 v = xp[i];
    s  += v.x + v.y + v.z + v.w;
    s2 += v.x*v.x + v.y*v.y + v.z*v.z + v.w*v.w;
  }
  #pragma unroll
  for (int o = 16; o; o >>= 1) {
    s  += __shfl_xor_sync(0xffffffffu, s, o);
    s2 += __shfl_xor_sync(0xffffffffu, s2, o);
  }
  __shared__ float rs[32], rs2[32];
  int wid = threadIdx.x >> 5;
  if ((threadIdx.x & 31) == 0) { rs[wid] = s; rs2[wid] = s2; }
  __syncthreads();
  if (threadIdx.x == 0) {
    float S = 0.f, S2 = 0.f;
    #pragma unroll
    for (int i = 0; i < 32; i++) { S += rs[i]; S2 += rs2[i]; }
    float mean = S * (1.f/16384.f);
    float var  = S2 * (1.f/16384.f) - mean*mean;
    g_stats[blockIdx.x] = make_float2(mean, rsqrtf(var + 1e-5f));
  }
}

// ---------------------------------------------------------------------------
// Kernel 2: fused GN-apply + Q/K/V GEMM, HMMA (validated R9 version).
// ---------------------------------------------------------------------------
__global__ __launch_bounds__(256) void qkv_kernel(
    const float* __restrict__ x,
    const float* __restrict__ gamma, const float* __restrict__ beta,
    const float* __restrict__ wq, const float* __restrict__ bq,
    const float* __restrict__ wk, const float* __restrict__ bk,
    const float* __restrict__ wv, const float* __restrict__ bv) {
  char* smem = dynsmem;
  uint32_t sb = smem_u32(smem);
  uint32_t sbW = sb + 32768;

  int b  = blockIdx.x >> 5;
  int n0 = (blockIdx.x & 31) << 7;
  int t  = threadIdx.x;
  int w  = t >> 5;
  int lane = t & 31;

  // stage normalized H tile [c][n0..n0+128) -> bf16, swizzled
  for (int i = t; i < 2048; i += 256) {
    int c = i >> 4, j8 = i & 15;
    float2 st = g_stats[b*32 + (c >> 2)];
    float ga = gamma[c] * st.y;
    float be = beta[c] - st.x * ga;
    const float4* hp = (const float4*)(x + ((size_t)b*CC + c)*NN + n0 + j8*8);
    float4 f0 = hp[0], f1 = hp[1];
    uint4 o;
    o.x = pk2(f0.x*ga+be, f0.y*ga+be); o.y = pk2(f0.z*ga+be, f0.w*ga+be);
    o.z = pk2(f1.x*ga+be, f1.y*ga+be); o.w = pk2(f1.z*ga+be, f1.w*ga+be);
    *(uint4*)(smem + c*256 + ((j8 ^ (c & 7)) << 4)) = o;
  }
  __syncthreads();

  // A-fragments of H^T (rows n, k = c) via trans ldmatrix
  uint32_t qa[8][4];
  {
    int krow_lo = ((lane >> 4) << 3) + (lane & 7);
    int mcol    = w*16 + (((lane >> 3) & 1) << 3);
    int mch     = mcol >> 3;
    #pragma unroll
    for (int ks = 0; ks < 8; ks++) {
      int krow = ks*16 + krow_lo;
      uint32_t a = sb + krow*256 + ((mch ^ (krow & 7)) << 4);
      ldsm_x4_t(qa[ks][0], qa[ks][1], qa[ks][2], qa[ks][3], a);
    }
  }

  const float* Wp[3] = {wq, wk, wv};
  const float* Bp[3] = {bq, bk, bv};
  __nv_bfloat16* Op[3] = {g_Qh + (size_t)b*NN*CC, g_Kh + (size_t)b*NN*CC,
                          g_Vh + (size_t)b*NN*CC};

  int rl   = lane & 7;
  int hf   = (lane >> 3) & 1;
  int nsel = (lane >> 4) & 1;
  int n_r  = n0 + w*16 + (lane >> 2);

  for (int m = 0; m < 3; m++) {
    __syncthreads();
    const float* wsrc = Wp[m];
    for (int i = t; i < 2048; i += 256) {
      int co = i >> 4, j8 = i & 15;
      const float4* pw = (const float4*)(wsrc + co*CC + j8*8);
      float4 f0 = pw[0], f1 = pw[1];
      uint4 o;
      o.x = pk2(f0.x, f0.y); o.y = pk2(f0.z, f0.w);
      o.z = pk2(f1.x, f1.y); o.w = pk2(f1.z, f1.w);
      *(uint4*)(smem + 32768 + co*256 + ((j8 ^ (co & 7)) << 4)) = o;
    }
    __syncthreads();

    __nv_bfloat16* out = Op[m];
    const float* bias = Bp[m];
    #pragma unroll
    for (int nb = 0; nb < 16; nb += 2) {
      float a0[4] = {0.f,0.f,0.f,0.f};
      float a1[4] = {0.f,0.f,0.f,0.f};
      #pragma unroll
      for (int ks = 0; ks < 8; ks++) {
        uint32_t bb[4];
        uint32_t a = sbW + ((nb + nsel)*8 + rl)*256 + (((2*ks + hf) ^ rl) << 4);
        ldsm_x4(bb[0], bb[1], bb[2], bb[3], a);
        mma_bf16(a0, qa[ks], bb,     a0);
        mma_bf16(a1, qa[ks], bb + 2, a1);
      }
      #pragma unroll
      for (int u = 0; u < 2; u++) {
        float* ac = u ? a1 : a0;
        int co0 = (nb + u)*8 + (lane & 3)*2;
        float b0 = bias[co0], b1 = bias[co0 + 1];
        *(uint32_t*)(out + (size_t)n_r*CC + co0)     = pk2(ac[0]+b0, ac[1]+b1);
        *(uint32_t*)(out + (size_t)(n_r+8)*CC + co0) = pk2(ac[2]+b0, ac[3]+b1);
      }
    }
  }
}

// ---------------------------------------------------------------------------
// Kernel 3: bf16 HMMA flash attention (validated R9 version).
// grid = 128 CTAs, 256 thr. Double-buffered cp.async K/V.
// ---------------------------------------------------------------------------
__global__ __launch_bounds__(256) void attn_kernel() {
  char* smem = dynsmem;
  uint32_t sb = smem_u32(smem);

  int t    = threadIdx.x;
  int w    = t >> 5;
  int lane = t & 31;
  int bid  = blockIdx.x;
  int b    = bid >> 6;
  int qt   = (bid >> 1) & 31;
  int sp   = bid & 1;
  int q0   = qt << 7;
  int kb0  = sp << 11;

  const __nv_bfloat16* Kg = g_Kh + (size_t)b*NN*CC;
  const __nv_bfloat16* Vg = g_Vh + (size_t)b*NN*CC;

  // ---- stage Q tile (swizzled) into buf1, load A-fragments ----
  for (int i = t; i < 2048; i += 256) {
    int row = i >> 4, cb = i & 15;
    *(uint4*)(smem + 32768 + row*256 + ((cb ^ (row & 7)) << 4)) =
        *(const uint4*)(g_Qh + ((size_t)b*NN + q0 + row)*CC + cb*8);
  }
  __syncthreads();

  // prefetch tile 0 into buf0
  {
    int kb = kb0;
    for (int i = t; i < 1024; i += 256) {
      int row = i >> 4, cb = i & 15;
      uint32_t d = sb + row*256 + ((cb ^ (row & 7)) << 4);
      cpa16(d,          Kg + ((size_t)(kb + row))*CC + cb*8);
      cpa16(d + 16384,  Vg + ((size_t)(kb + row))*CC + cb*8);
    }
    cp_commit();
  }

  uint32_t qa[8][4];
  {
    int row = w*16 + (lane & 15);
    int kc  = (lane >> 4) & 1;
    #pragma unroll
    for (int ks = 0; ks < 8; ks++) {
      uint32_t a = sb + 32768 + row*256 + (((2*ks + kc) ^ (row & 7)) << 4);
      ldsm_x4(qa[ks][0], qa[ks][1], qa[ks][2], qa[ks][3], a);
    }
  }
  __syncthreads();   // Q frags in regs; buf1 free

  // prefetch tile 1 into buf1
  {
    int kb = kb0 + 64;
    for (int i = t; i < 1024; i += 256) {
      int row = i >> 4, cb = i & 15;
      uint32_t d = sb + 32768 + row*256 + ((cb ^ (row & 7)) << 4);
      cpa16(d,          Kg + ((size_t)(kb + row))*CC + cb*8);
      cpa16(d + 16384,  Vg + ((size_t)(kb + row))*CC + cb*8);
    }
    cp_commit();
  }

  int rl   = lane & 7;
  int hf   = (lane >> 3) & 1;
  int nsel = (lane >> 4) & 1;

  float oacc[16][4];
  #pragma unroll
  for (int nb = 0; nb < 16; nb++)
    { oacc[nb][0]=0.f; oacc[nb][1]=0.f; oacc[nb][2]=0.f; oacc[nb][3]=0.f; }
  float l0 = 0.f, l1 = 0.f;

  for (int kt = 0; kt < 32; kt++) {
    if (kt < 31) cp_wait<1>(); else cp_wait<0>();
    __syncthreads();

    uint32_t Ks = sb + (uint32_t)(kt & 1)*32768;
    uint32_t Vs = Ks + 16384;

    // ---- S = Q K^T ----
    float sacc[8][4];
    #pragma unroll
    for (int nb = 0; nb < 8; nb += 2) {
      float* s0 = sacc[nb];
      float* s1 = sacc[nb+1];
      s0[0]=0.f; s0[1]=0.f; s0[2]=0.f; s0[3]=0.f;
      s1[0]=0.f; s1[1]=0.f; s1[2]=0.f; s1[3]=0.f;
      #pragma unroll
      for (int ks = 0; ks < 8; ks++) {
        uint32_t bb[4];
        uint32_t a = Ks + (((nb + nsel)*8 + rl) << 8) + (((2*ks + hf) ^ rl) << 4);
        ldsm_x4(bb[0], bb[1], bb[2], bb[3], a);
        mma_bf16(s0, qa[ks], bb,     s0);
        mma_bf16(s1, qa[ks], bb + 2, s1);
      }
    }

    // ---- exp + row sums ----
    float rs0 = 0.f, rs1 = 0.f;
    #pragma unroll
    for (int nb = 0; nb < 8; nb++) {
      float p0 = __expf(fminf(sacc[nb][0]*SCALE, 80.f));
      float p1 = __expf(fminf(sacc[nb][1]*SCALE, 80.f));
      float p2 = __expf(fminf(sacc[nb][2]*SCALE, 80.f));
      float p3 = __expf(fminf(sacc[nb][3]*SCALE, 80.f));
      sacc[nb][0]=p0; sacc[nb][1]=p1; sacc[nb][2]=p2; sacc[nb][3]=p3;
      rs0 += p0 + p1;
      rs1 += p2 + p3;
    }
    rs0 += __shfl_xor_sync(0xffffffffu, rs0, 1);
    rs0 += __shfl_xor_sync(0xffffffffu, rs0, 2);
    rs1 += __shfl_xor_sync(0xffffffffu, rs1, 1);
    rs1 += __shfl_xor_sync(0xffffffffu, rs1, 2);
    l0 += rs0;
    l1 += rs1;

    // ---- O += P V ----
    #pragma unroll
    for (int ks = 0; ks < 4; ks++) {
      uint32_t pa[4];
      pa[0] = pk2(sacc[2*ks][0],   sacc[2*ks][1]);
      pa[1] = pk2(sacc[2*ks][2],   sacc[2*ks][3]);
      pa[2] = pk2(sacc[2*ks+1][0], sacc[2*ks+1][1]);
      pa[3] = pk2(sacc[2*ks+1][2], sacc[2*ks+1][3]);
      int vrow = ks*16 + (lane & 15);
      uint32_t abase = Vs + vrow*256;
      uint32_t sw = (uint32_t)(vrow & 7) << 4;
      #pragma unroll
      for (int nb = 0; nb < 16; nb += 2) {
        uint32_t bb[4];
        uint32_t a = abase + (((uint32_t)((nb + nsel) << 4)) ^ sw);
        ldsm_x4_t(bb[0], bb[1], bb[2], bb[3], a);
        mma_bf16(oacc[nb],   pa, bb,     oacc[nb]);
        mma_bf16(oacc[nb+1], pa, bb + 2, oacc[nb+1]);
      }
    }

    __syncthreads();
    if (kt + 2 < 32) {
      int kb = kb0 + ((kt + 2) << 6);
      uint32_t base = sb + (uint32_t)(kt & 1)*32768;
      for (int i = t; i < 1024; i += 256) {
        int row = i >> 4, cb = i & 15;
        uint32_t d = base + row*256 + ((cb ^ (row & 7)) << 4);
        cpa16(d,          Kg + ((size_t)(kb + row))*CC + cb*8);
        cpa16(d + 16384,  Vg + ((size_t)(kb + row))*CC + cb*8);
      }
      cp_commit();
    }
  }

  // ---- epilogue: bf16 partial O and fp32 l ----
  int r0 = q0 + w*16 + (lane >> 2);
  __nv_bfloat16* Og = g_Opb + ((size_t)(b*2 + sp)*NN + r0)*CC;
  int col = (lane & 3)*2;
  #pragma unroll
  for (int nb = 0; nb < 16; nb++) {
    *(uint32_t*)(Og + nb*8 + col)                = pk2(oacc[nb][0], oacc[nb][1]);
    *(uint32_t*)(Og + (size_t)8*CC + nb*8 + col) = pk2(oacc[nb][2], oacc[nb][3]);
  }
  if ((lane & 3) == 0) {
    g_l[(size_t)(b*2 + sp)*NN + r0]     = l0;
    g_l[(size_t)(b*2 + sp)*NN + r0 + 8] = l1;
  }
}

// ---------------------------------------------------------------------------
// Kernel 4: combine + projection + bias + residual, HMMA.
// 64-token tiles -> grid = BB*64 = 128 CTAs, 256 thr.
// Warps 0-3: rows 0-63, out-blocks 0-7; warps 4-7: same rows, blocks 8-15.
// SMEM: A [64][256B] @0 (16KB), W [128][256B] @16384 (32KB);
//       epilogue reuses smem as Ot[128co][68]f (34816 B). Total 49152.
// ---------------------------------------------------------------------------
__global__ __launch_bounds__(256) void proj_kernel(
    const float* __restrict__ x,
    const float* __restrict__ wp,
    const float* __restrict__ bp,
    float* __restrict__ outp) {
  char* smem = dynsmem;
  uint32_t sb = smem_u32(smem);
  uint32_t sbW = sb + 16384;
  float* Ot = (float*)smem;

  int b  = blockIdx.x >> 6;
  int n0 = (blockIdx.x & 63) << 6;
  int t  = threadIdx.x;
  int w  = t >> 5;
  int lane = t & 31;

  // stage A tile (64 rows) = (O_sp0 + O_sp1) / (l0 + l1), bf16, swizzled
  for (int i = t; i < 1024; i += 256) {
    int row = i >> 4, cb = i & 15;
    int n = n0 + row;
    float inv = 1.f / (g_l[(size_t)(b*2)*NN + n] + g_l[(size_t)(b*2+1)*NN + n]);
    uint4 ua = *(const uint4*)(g_Opb + ((size_t)(b*2)*NN + n)*CC + cb*8);
    uint4 uc = *(const uint4*)(g_Opb + ((size_t)(b*2+1)*NN + n)*CC + cb*8);
    const __nv_bfloat162* pa = (const __nv_bfloat162*)&ua;
    const __nv_bfloat162* pc = (const __nv_bfloat162*)&uc;
    uint4 o;
    uint32_t* po = (uint32_t*)&o;
    #pragma unroll
    for (int j = 0; j < 4; j++) {
      float2 fa = __bfloat1622float2(pa[j]);
      float2 fc = __bfloat1622float2(pc[j]);
      po[j] = pk2((fa.x + fc.x)*inv, (fa.y + fc.y)*inv);
    }
    *(uint4*)(smem + row*256 + ((cb ^ (row & 7)) << 4)) = o;
  }
  // stage wp fp32 -> bf16 [co][c]
  for (int i = t; i < 2048; i += 256) {
    int co = i >> 4, j8 = i & 15;
    const float4* pw = (const float4*)(wp + co*CC + j8*8);
    float4 f0 = pw[0], f1 = pw[1];
    uint4 o;
    o.x = pk2(f0.x, f0.y); o.y = pk2(f0.z, f0.w);
    o.z = pk2(f1.x, f1.y); o.w = pk2(f1.z, f1.w);
    *(uint4*)(smem + 16384 + co*256 + ((j8 ^ (co & 7)) << 4)) = o;
  }
  __syncthreads();

  // A-fragments: rows (w&3)*16..+16
  uint32_t qa[8][4];
  {
    int row = (w & 3)*16 + (lane & 15);
    int kc  = (lane >> 4) & 1;
    #pragma unroll
    for (int ks = 0; ks < 8; ks++) {
      uint32_t a = sb + row*256 + (((2*ks + kc) ^ (row & 7)) << 4);
      ldsm_x4(qa[ks][0], qa[ks][1], qa[ks][2], qa[ks][3], a);
    }
  }

  int rl    = lane & 7;
  int hf    = (lane >> 3) & 1;
  int nsel  = (lane >> 4) & 1;
  int nbase = (w >> 2)*8;

  float acc[8][4];
  #pragma unroll
  for (int nb = 0; nb < 8; nb += 2) {
    float* a0 = acc[nb];
    float* a1 = acc[nb+1];
    a0[0]=0.f; a0[1]=0.f; a0[2]=0.f; a0[3]=0.f;
    a1[0]=0.f; a1[1]=0.f; a1[2]=0.f; a1[3]=0.f;
    #pragma unroll
    for (int ks = 0; ks < 8; ks++) {
      uint32_t bb[4];
      uint32_t a = sbW + ((nbase + nb + nsel)*8 + rl)*256 + (((2*ks + hf) ^ rl) << 4);
      ldsm_x4(bb[0], bb[1], bb[2], bb[3], a);
      mma_bf16(a0, qa[ks], bb,     a0);
      mma_bf16(a1, qa[ks], bb + 2, a1);
    }
  }
  __syncthreads();   // done with A/W; reuse smem as Ot[128co][68]

  int nl = (w & 3)*16 + (lane >> 2);
  #pragma unroll
  for (int nb = 0; nb < 8; nb++) {
    int co0 = (nbase + nb)*8 + (lane & 3)*2;
    Ot[co0*68 + nl]           = acc[nb][0];
    Ot[(co0 + 1)*68 + nl]     = acc[nb][1];
    Ot[co0*68 + nl + 8]       = acc[nb][2];
    Ot[(co0 + 1)*68 + nl + 8] = acc[nb][3];
  }
  __syncthreads();

  // coalesced output: out[b][co][n0..n0+64) = x + Ot + bias
  for (int i = t; i < 2048; i += 256) {
    int co = i >> 4, q4 = i & 15;
    float bias = bp[co];
    size_t base = (size_t)b*CC*NN + (size_t)co*NN + n0 + q4*4;
    float4 xv = *(const float4*)&x[base];
    float4 hv = *(float4*)&Ot[co*68 + q4*4];
    float4 o;
    o.x = xv.x + hv.x + bias;
    o.y = xv.y + hv.y + bias;
    o.z = xv.z + hv.z + bias;
    o.w = xv.w + hv.w + bias;
    *(float4*)&outp[base] = o;
  }
}

// ---------------------------------------------------------------------------
extern "C" void kernel_launch(void* const* d_in, const int* in_sizes, int n_in,
                              void* d_out, int out_size) {
  (void)in_sizes; (void)n_in; (void)out_size;
  const float* x    = (const float*)d_in[0];
  const float* gn_w = (const float*)d_in[1];
  const float* gn_b = (const float*)d_in[2];
  const float* wq   = (const float*)d_in[3];
  const float* bq   = (const float*)d_in[4];
  const float* wk   = (const float*)d_in[5];
  const float* bk   = (const float*)d_in[6];
  const float* wv   = (const float*)d_in[7];
  const float* bv   = (const float*)d_in[8];
  const float* wp   = (const float*)d_in[9];
  const float* bp   = (const float*)d_in[10];
  float* out = (float*)d_out;

  const int QKV_SMEM  = 65536;
  const int ATTN_SMEM = 65536;
  const int PROJ_SMEM = 49152;
  cudaFuncSetAttribute(qkv_kernel,  cudaFuncAttributeMaxDynamicSharedMemorySize, QKV_SMEM);
  cudaFuncSetAttribute(attn_kernel, cudaFuncAttributeMaxDynamicSharedMemorySize, ATTN_SMEM);
  cudaFuncSetAttribute(proj_kernel, cudaFuncAttributeMaxDynamicSharedMemorySize, PROJ_SMEM);

  gn_stats_kernel<<<64, 1024>>>(x);
  qkv_kernel<<<64, 256, QKV_SMEM>>>(x, gn_w, gn_b, wq, bq, wk, bk, wv, bv);
  attn_kernel<<<128, 256, ATTN_SMEM>>>();
  proj_kernel<<<128, 256, PROJ_SMEM>>>(x, wp, bp, out);
}

// round 14
// speedup vs baseline: 1.3073x; 1.1092x over previous
#include <cuda_runtime.h>
#include <cuda_bf16.h>
#include <stdint.h>

#define BB 2
#define CC 128
#define NN 4096
#define SCALE 0.08838834764831845f   // 128^-0.5

// ---------------- scratch (no allocations allowed) -------------------------
__device__ float2         g_part[BB*32*4];     // per (b,group,quarter): sum, sumsq
__device__ __nv_bfloat16  g_Wb[4*CC*CC];       // bf16 weights: wq,wk,wv,wp [co][c]
__device__ __nv_bfloat16  g_Qh[BB*NN*CC];      // [b][n][c] bf16
__device__ __nv_bfloat16  g_Kh[BB*NN*CC];      // [b][n][c] bf16
__device__ __nv_bfloat16  g_Vh[BB*NN*CC];      // [b][n][c] bf16
__device__ __nv_bfloat16  g_Opb[BB*2*NN*CC];   // partial O, [b][sp][n][c] bf16
__device__ float          g_l [BB*2*NN];       // partial softmax sums

extern __shared__ char dynsmem[];

// ---------------- PTX helpers (baseline-safe, sm_80-era) -------------------
__device__ __forceinline__ uint32_t smem_u32(const void* p) {
  uint32_t a;
  asm("{ .reg .u64 t; cvta.to.shared.u64 t, %1; cvt.u32.u64 %0, t; }"
      : "=r"(a) : "l"(p));
  return a;
}
__device__ __forceinline__ void ldsm_x4(uint32_t& r0, uint32_t& r1,
                                        uint32_t& r2, uint32_t& r3, uint32_t a) {
  asm volatile("ldmatrix.sync.aligned.m8n8.x4.shared.b16 {%0,%1,%2,%3}, [%4];"
               : "=r"(r0), "=r"(r1), "=r"(r2), "=r"(r3) : "r"(a));
}
__device__ __forceinline__ void ldsm_x4_t(uint32_t& r0, uint32_t& r1,
                                          uint32_t& r2, uint32_t& r3, uint32_t a) {
  asm volatile("ldmatrix.sync.aligned.m8n8.x4.trans.shared.b16 {%0,%1,%2,%3}, [%4];"
               : "=r"(r0), "=r"(r1), "=r"(r2), "=r"(r3) : "r"(a));
}
__device__ __forceinline__ void mma_bf16(float* d, const uint32_t* a,
                                         const uint32_t* b, const float* c) {
  asm volatile(
    "mma.sync.aligned.m16n8k16.row.col.f32.bf16.bf16.f32 "
    "{%0,%1,%2,%3}, {%4,%5,%6,%7}, {%8,%9}, {%10,%11,%12,%13};"
    : "=f"(d[0]), "=f"(d[1]), "=f"(d[2]), "=f"(d[3])
    : "r"(a[0]), "r"(a[1]), "r"(a[2]), "r"(a[3]),
      "r"(b[0]), "r"(b[1]),
      "f"(c[0]), "f"(c[1]), "f"(c[2]), "f"(c[3]));
}
__device__ __forceinline__ uint32_t pk2(float lo, float hi) {
  uint32_t r;
  asm("cvt.rn.bf16x2.f32 %0, %1, %2;" : "=r"(r) : "f"(hi), "f"(lo));
  return r;
}
__device__ __forceinline__ void cpa16(uint32_t dst, const void* src) {
  asm volatile("cp.async.cg.shared.global [%0], [%1], 16;" :: "r"(dst), "l"(src));
}
__device__ __forceinline__ void cp_commit() {
  asm volatile("cp.async.commit_group;" ::: "memory");
}
template <int N> __device__ __forceinline__ void cp_wait() {
  asm volatile("cp.async.wait_group %0;" :: "n"(N) : "memory");
}

// ---------------------------------------------------------------------------
// Kernel 1: setup — GN partial stats (blocks 0..255) + weight bf16 convert
// (blocks 256..287). grid = 288, 256 thr.
// ---------------------------------------------------------------------------
__global__ __launch_bounds__(256) void setup_kernel(
    const float* __restrict__ x,
    const float* __restrict__ wq, const float* __restrict__ wk,
    const float* __restrict__ wv, const float* __restrict__ wp) {
  int bid = blockIdx.x;
  int t   = threadIdx.x;
  if (bid >= 256) {
    int j = (bid - 256)*256 + t;          // 0..8191 uint4 outputs
    int widx = j >> 11;                   // 2048 uint4 per weight
    const float* ws = widx == 0 ? wq : widx == 1 ? wk : widx == 2 ? wv : wp;
    int jj = j & 2047;
    const float4* pw = (const float4*)(ws + (jj >> 4)*CC + (jj & 15)*8);
    float4 f0 = pw[0], f1 = pw[1];
    uint4 o;
    o.x = pk2(f0.x, f0.y); o.y = pk2(f0.z, f0.w);
    o.z = pk2(f1.x, f1.y); o.w = pk2(f1.z, f1.w);
    ((uint4*)g_Wb)[j] = o;
    return;
  }
  int b = bid >> 7, g = (bid >> 2) & 31, qtr = bid & 3;
  const float4* xp = (const float4*)(x + ((size_t)b*CC + g*4)*NN) + qtr*1024;
  float s = 0.f, s2 = 0.f;
  for (int i = t; i < 1024; i += 256) {
    float4 v = xp[i];
    s  += v.x + v.y + v.z + v.w;
    s2 += v.x*v.x + v.y*v.y + v.z*v.z + v.w*v.w;
  }
  #pragma unroll
  for (int o = 16; o; o >>= 1) {
    s  += __shfl_xor_sync(0xffffffffu, s, o);
    s2 += __shfl_xor_sync(0xffffffffu, s2, o);
  }
  __shared__ float rs[8], rs2[8];
  int wid = t >> 5;
  if ((t & 31) == 0) { rs[wid] = s; rs2[wid] = s2; }
  __syncthreads();
  if (t == 0) {
    float S = 0.f, S2 = 0.f;
    #pragma unroll
    for (int i = 0; i < 8; i++) { S += rs[i]; S2 += rs2[i]; }
    g_part[bid] = make_float2(S, S2);
  }
}

// ---------------------------------------------------------------------------
// Kernel 2: fused GN-apply + Q/K/V GEMM, HMMA, double-buffered bf16 weights.
// grid = BB*32 (128-token tiles), 256 thr.
// SMEM: H 32KB @0, Wbuf0 @32768, Wbuf1 @65536, sGA @98304, sBE @98816.
// ---------------------------------------------------------------------------
__global__ __launch_bounds__(256) void qkv_kernel(
    const float* __restrict__ x,
    const float* __restrict__ gamma, const float* __restrict__ beta,
    const float* __restrict__ bq, const float* __restrict__ bk,
    const float* __restrict__ bv) {
  char* smem = dynsmem;
  uint32_t sb = smem_u32(smem);
  float* sGA = (float*)(smem + 98304);
  float* sBE = (float*)(smem + 98816);

  int b  = blockIdx.x >> 5;
  int n0 = (blockIdx.x & 31) << 7;
  int t  = threadIdx.x;
  int w  = t >> 5;
  int lane = t & 31;

  // finalize GN stats per channel
  if (t < 128) {
    int base = (b << 7) | ((t >> 2) << 2);
    float S = 0.f, S2 = 0.f;
    #pragma unroll
    for (int j = 0; j < 4; j++) {
      float2 p = g_part[base + j];
      S += p.x; S2 += p.y;
    }
    float mean = S * (1.f/16384.f);
    float rstd = rsqrtf(S2 * (1.f/16384.f) - mean*mean + 1e-5f);
    float ga = gamma[t] * rstd;
    sGA[t] = ga;
    sBE[t] = beta[t] - mean * ga;
  }
  // prefetch W0 (bf16) into buf0
  {
    const uint4* Wg = (const uint4*)g_Wb;
    for (int i = t; i < 2048; i += 256) {
      int co = i >> 4, cb = i & 15;
      cpa16(sb + 32768 + co*256 + ((cb ^ (co & 7)) << 4), Wg + co*16 + cb);
    }
    cp_commit();
  }
  __syncthreads();   // sGA/sBE visible

  // stage normalized H tile [c][n0..n0+128) -> bf16, swizzled
  for (int i = t; i < 2048; i += 256) {
    int c = i >> 4, j8 = i & 15;
    float ga = sGA[c], be = sBE[c];
    const float4* hp = (const float4*)(x + ((size_t)b*CC + c)*NN + n0 + j8*8);
    float4 f0 = hp[0], f1 = hp[1];
    uint4 o;
    o.x = pk2(f0.x*ga+be, f0.y*ga+be); o.y = pk2(f0.z*ga+be, f0.w*ga+be);
    o.z = pk2(f1.x*ga+be, f1.y*ga+be); o.w = pk2(f1.z*ga+be, f1.w*ga+be);
    *(uint4*)(smem + c*256 + ((j8 ^ (c & 7)) << 4)) = o;
  }
  __syncthreads();

  // A-fragments of H^T (rows n, k = c) via trans ldmatrix
  uint32_t qa[8][4];
  {
    int krow_lo = ((lane >> 4) << 3) + (lane & 7);
    int mch     = (w*16 + (((lane >> 3) & 1) << 3)) >> 3;
    #pragma unroll
    for (int ks = 0; ks < 8; ks++) {
      int krow = ks*16 + krow_lo;
      uint32_t a = sb + krow*256 + ((mch ^ (krow & 7)) << 4);
      ldsm_x4_t(qa[ks][0], qa[ks][1], qa[ks][2], qa[ks][3], a);
    }
  }

  const float* Bp[3] = {bq, bk, bv};
  __nv_bfloat16* Op[3] = {g_Qh + (size_t)b*NN*CC, g_Kh + (size_t)b*NN*CC,
                          g_Vh + (size_t)b*NN*CC};

  int rl   = lane & 7;
  int hf   = (lane >> 3) & 1;
  int nsel = (lane >> 4) & 1;
  int n_r  = n0 + w*16 + (lane >> 2);

  for (int m = 0; m < 3; m++) {
    cp_wait<0>();
    __syncthreads();   // W(m) ready; everyone done with previous buffer reads

    if (m < 2) {       // prefetch W(m+1) into the other buffer
      const uint4* Wg = (const uint4*)g_Wb + (m + 1)*2048;   // FIX: 2048 uint4/weight
      uint32_t dstb = sb + 32768 + (uint32_t)((m + 1) & 1)*32768;
      for (int i = t; i < 2048; i += 256) {
        int co = i >> 4, cb = i & 15;
        cpa16(dstb + co*256 + ((cb ^ (co & 7)) << 4), Wg + co*16 + cb);
      }
      cp_commit();
    }

    uint32_t sbW = sb + 32768 + (uint32_t)(m & 1)*32768;
    __nv_bfloat16* out = Op[m];
    const float* bias = Bp[m];
    #pragma unroll
    for (int nb = 0; nb < 16; nb += 2) {
      float a0[4] = {0.f,0.f,0.f,0.f};
      float a1[4] = {0.f,0.f,0.f,0.f};
      #pragma unroll
      for (int ks = 0; ks < 8; ks++) {
        uint32_t bb[4];
        uint32_t a = sbW + ((nb + nsel)*8 + rl)*256 + (((2*ks + hf) ^ rl) << 4);
        ldsm_x4(bb[0], bb[1], bb[2], bb[3], a);
        mma_bf16(a0, qa[ks], bb,     a0);
        mma_bf16(a1, qa[ks], bb + 2, a1);
      }
      #pragma unroll
      for (int u = 0; u < 2; u++) {
        float* ac = u ? a1 : a0;
        int co0 = (nb + u)*8 + (lane & 3)*2;
        float b0 = bias[co0], b1 = bias[co0 + 1];
        *(uint32_t*)(out + (size_t)n_r*CC + co0)     = pk2(ac[0]+b0, ac[1]+b1);
        *(uint32_t*)(out + (size_t)(n_r+8)*CC + co0) = pk2(ac[2]+b0, ac[3]+b1);
      }
    }
  }
}

// ---------------------------------------------------------------------------
// Kernel 3: bf16 HMMA flash attention (validated R12 version, unchanged).
// ---------------------------------------------------------------------------
__global__ __launch_bounds__(256) void attn_kernel() {
  char* smem = dynsmem;
  uint32_t sb = smem_u32(smem);

  int t    = threadIdx.x;
  int w    = t >> 5;
  int lane = t & 31;
  int bid  = blockIdx.x;
  int b    = bid >> 6;
  int qt   = (bid >> 1) & 31;
  int sp   = bid & 1;
  int q0   = qt << 7;
  int kb0  = sp << 11;

  const __nv_bfloat16* Kg = g_Kh + (size_t)b*NN*CC;
  const __nv_bfloat16* Vg = g_Vh + (size_t)b*NN*CC;

  for (int i = t; i < 2048; i += 256) {
    int row = i >> 4, cb = i & 15;
    *(uint4*)(smem + 32768 + row*256 + ((cb ^ (row & 7)) << 4)) =
        *(const uint4*)(g_Qh + ((size_t)b*NN + q0 + row)*CC + cb*8);
  }
  __syncthreads();

  {
    int kb = kb0;
    for (int i = t; i < 1024; i += 256) {
      int row = i >> 4, cb = i & 15;
      uint32_t d = sb + row*256 + ((cb ^ (row & 7)) << 4);
      cpa16(d,          Kg + ((size_t)(kb + row))*CC + cb*8);
      cpa16(d + 16384,  Vg + ((size_t)(kb + row))*CC + cb*8);
    }
    cp_commit();
  }

  uint32_t qa[8][4];
  {
    int row = w*16 + (lane & 15);
    int kc  = (lane >> 4) & 1;
    #pragma unroll
    for (int ks = 0; ks < 8; ks++) {
      uint32_t a = sb + 32768 + row*256 + (((2*ks + kc) ^ (row & 7)) << 4);
      ldsm_x4(qa[ks][0], qa[ks][1], qa[ks][2], qa[ks][3], a);
    }
  }
  __syncthreads();

  {
    int kb = kb0 + 64;
    for (int i = t; i < 1024; i += 256) {
      int row = i >> 4, cb = i & 15;
      uint32_t d = sb + 32768 + row*256 + ((cb ^ (row & 7)) << 4);
      cpa16(d,          Kg + ((size_t)(kb + row))*CC + cb*8);
      cpa16(d + 16384,  Vg + ((size_t)(kb + row))*CC + cb*8);
    }
    cp_commit();
  }

  int rl   = lane & 7;
  int hf   = (lane >> 3) & 1;
  int nsel = (lane >> 4) & 1;

  float oacc[16][4];
  #pragma unroll
  for (int nb = 0; nb < 16; nb++)
    { oacc[nb][0]=0.f; oacc[nb][1]=0.f; oacc[nb][2]=0.f; oacc[nb][3]=0.f; }
  float l0 = 0.f, l1 = 0.f;

  for (int kt = 0; kt < 32; kt++) {
    if (kt < 31) cp_wait<1>(); else cp_wait<0>();
    __syncthreads();

    uint32_t Ks = sb + (uint32_t)(kt & 1)*32768;
    uint32_t Vs = Ks + 16384;

    float sacc[8][4];
    #pragma unroll
    for (int nb = 0; nb < 8; nb += 2) {
      float* s0 = sacc[nb];
      float* s1 = sacc[nb+1];
      s0[0]=0.f; s0[1]=0.f; s0[2]=0.f; s0[3]=0.f;
      s1[0]=0.f; s1[1]=0.f; s1[2]=0.f; s1[3]=0.f;
      #pragma unroll
      for (int ks = 0; ks < 8; ks++) {
        uint32_t bb[4];
        uint32_t a = Ks + (((nb + nsel)*8 + rl) << 8) + (((2*ks + hf) ^ rl) << 4);
        ldsm_x4(bb[0], bb[1], bb[2], bb[3], a);
        mma_bf16(s0, qa[ks], bb,     s0);
        mma_bf16(s1, qa[ks], bb + 2, s1);
      }
    }

    float rs0 = 0.f, rs1 = 0.f;
    #pragma unroll
    for (int nb = 0; nb < 8; nb++) {
      float p0 = __expf(fminf(sacc[nb][0]*SCALE, 80.f));
      float p1 = __expf(fminf(sacc[nb][1]*SCALE, 80.f));
      float p2 = __expf(fminf(sacc[nb][2]*SCALE, 80.f));
      float p3 = __expf(fminf(sacc[nb][3]*SCALE, 80.f));
      sacc[nb][0]=p0; sacc[nb][1]=p1; sacc[nb][2]=p2; sacc[nb][3]=p3;
      rs0 += p0 + p1;
      rs1 += p2 + p3;
    }
    rs0 += __shfl_xor_sync(0xffffffffu, rs0, 1);
    rs0 += __shfl_xor_sync(0xffffffffu, rs0, 2);
    rs1 += __shfl_xor_sync(0xffffffffu, rs1, 1);
    rs1 += __shfl_xor_sync(0xffffffffu, rs1, 2);
    l0 += rs0;
    l1 += rs1;

    #pragma unroll
    for (int ks = 0; ks < 4; ks++) {
      uint32_t pa[4];
      pa[0] = pk2(sacc[2*ks][0],   sacc[2*ks][1]);
      pa[1] = pk2(sacc[2*ks][2],   sacc[2*ks][3]);
      pa[2] = pk2(sacc[2*ks+1][0], sacc[2*ks+1][1]);
      pa[3] = pk2(sacc[2*ks+1][2], sacc[2*ks+1][3]);
      int vrow = ks*16 + (lane & 15);
      uint32_t abase = Vs + vrow*256;
      uint32_t sw = (uint32_t)(vrow & 7) << 4;
      #pragma unroll
      for (int nb = 0; nb < 16; nb += 2) {
        uint32_t bb[4];
        uint32_t a = abase + (((uint32_t)((nb + nsel) << 4)) ^ sw);
        ldsm_x4_t(bb[0], bb[1], bb[2], bb[3], a);
        mma_bf16(oacc[nb],   pa, bb,     oacc[nb]);
        mma_bf16(oacc[nb+1], pa, bb + 2, oacc[nb+1]);
      }
    }

    __syncthreads();
    if (kt + 2 < 32) {
      int kb = kb0 + ((kt + 2) << 6);
      uint32_t base = sb + (uint32_t)(kt & 1)*32768;
      for (int i = t; i < 1024; i += 256) {
        int row = i >> 4, cb = i & 15;
        uint32_t d = base + row*256 + ((cb ^ (row & 7)) << 4);
        cpa16(d,          Kg + ((size_t)(kb + row))*CC + cb*8);
        cpa16(d + 16384,  Vg + ((size_t)(kb + row))*CC + cb*8);
      }
      cp_commit();
    }
  }

  int r0 = q0 + w*16 + (lane >> 2);
  __nv_bfloat16* Og = g_Opb + ((size_t)(b*2 + sp)*NN + r0)*CC;
  int col = (lane & 3)*2;
  #pragma unroll
  for (int nb = 0; nb < 16; nb++) {
    *(uint32_t*)(Og + nb*8 + col)                = pk2(oacc[nb][0], oacc[nb][1]);
    *(uint32_t*)(Og + (size_t)8*CC + nb*8 + col) = pk2(oacc[nb][2], oacc[nb][3]);
  }
  if ((lane & 3) == 0) {
    g_l[(size_t)(b*2 + sp)*NN + r0]     = l0;
    g_l[(size_t)(b*2 + sp)*NN + r0 + 8] = l1;
  }
}

// ---------------------------------------------------------------------------
// Kernel 4: combine + projection + bias + residual, HMMA.
// 32-token tiles -> grid = BB*128 = 256 CTAs, 256 thr.
// Warp w: rows (w&1)*16.., out-blocks nbase=(w>>1)*4 .. +4.
// SMEM: A [32][256B] @0 (8KB), W @8192 (32KB); epi Ot[128][36]f. 40960 B.
// ---------------------------------------------------------------------------
__global__ __launch_bounds__(256) void proj_kernel(
    const float* __restrict__ x,
    const float* __restrict__ bp,
    float* __restrict__ outp) {
  char* smem = dynsmem;
  uint32_t sb = smem_u32(smem);
  uint32_t sbW = sb + 8192;
  float* Ot = (float*)smem;

  int b  = blockIdx.x >> 7;
  int n0 = (blockIdx.x & 127) << 5;
  int t  = threadIdx.x;
  int w  = t >> 5;
  int lane = t & 31;

  // prefetch W (wp bf16) via cp.async, overlapped with A combine staging
  {
    const uint4* Wg = (const uint4*)g_Wb + 3*2048;   // FIX: 2048 uint4/weight
    for (int i = t; i < 2048; i += 256) {
      int co = i >> 4, cb = i & 15;
      cpa16(sbW + co*256 + ((cb ^ (co & 7)) << 4), Wg + co*16 + cb);
    }
    cp_commit();
  }

  // stage A tile (32 rows) = (O_sp0 + O_sp1) / (l0 + l1), bf16, swizzled
  for (int i = t; i < 512; i += 256) {
    int row = i >> 4, cb = i & 15;
    int n = n0 + row;
    float inv = 1.f / (g_l[(size_t)(b*2)*NN + n] + g_l[(size_t)(b*2+1)*NN + n]);
    uint4 ua = *(const uint4*)(g_Opb + ((size_t)(b*2)*NN + n)*CC + cb*8);
    uint4 uc = *(const uint4*)(g_Opb + ((size_t)(b*2+1)*NN + n)*CC + cb*8);
    const __nv_bfloat162* pa = (const __nv_bfloat162*)&ua;
    const __nv_bfloat162* pc = (const __nv_bfloat162*)&uc;
    uint4 o;
    uint32_t* po = (uint32_t*)&o;
    #pragma unroll
    for (int j = 0; j < 4; j++) {
      float2 fa = __bfloat1622float2(pa[j]);
      float2 fc = __bfloat1622float2(pc[j]);
      po[j] = pk2((fa.x + fc.x)*inv, (fa.y + fc.y)*inv);
    }
    *(uint4*)(smem + row*256 + ((cb ^ (row & 7)) << 4)) = o;
  }
  cp_wait<0>();
  __syncthreads();

  // A-fragments: rows (w&1)*16..+16
  uint32_t qa[8][4];
  {
    int row = (w & 1)*16 + (lane & 15);
    int kc  = (lane >> 4) & 1;
    #pragma unroll
    for (int ks = 0; ks < 8; ks++) {
      uint32_t a = sb + row*256 + (((2*ks + kc) ^ (row & 7)) << 4);
      ldsm_x4(qa[ks][0], qa[ks][1], qa[ks][2], qa[ks][3], a);
    }
  }

  int rl    = lane & 7;
  int hf    = (lane >> 3) & 1;
  int nsel  = (lane >> 4) & 1;
  int nbase = (w >> 1)*4;

  float acc[4][4];
  #pragma unroll
  for (int nb = 0; nb < 4; nb += 2) {
    float* a0 = acc[nb];
    float* a1 = acc[nb+1];
    a0[0]=0.f; a0[1]=0.f; a0[2]=0.f; a0[3]=0.f;
    a1[0]=0.f; a1[1]=0.f; a1[2]=0.f; a1[3]=0.f;
    #pragma unroll
    for (int ks = 0; ks < 8; ks++) {
      uint32_t bb[4];
      uint32_t a = sbW + ((nbase + nb + nsel)*8 + rl)*256 + (((2*ks + hf) ^ rl) << 4);
      ldsm_x4(bb[0], bb[1], bb[2], bb[3], a);
      mma_bf16(a0, qa[ks], bb,     a0);
      mma_bf16(a1, qa[ks], bb + 2, a1);
    }
  }
  __syncthreads();   // done with A/W; reuse smem as Ot[128co][36]

  int nl = (w & 1)*16 + (lane >> 2);
  #pragma unroll
  for (int nb = 0; nb < 4; nb++) {
    int co0 = (nbase + nb)*8 + (lane & 3)*2;
    Ot[co0*36 + nl]           = acc[nb][0];
    Ot[(co0 + 1)*36 + nl]     = acc[nb][1];
    Ot[co0*36 + nl + 8]       = acc[nb][2];
    Ot[(co0 + 1)*36 + nl + 8] = acc[nb][3];
  }
  __syncthreads();

  // coalesced output: out[b][co][n0..n0+32) = x + Ot + bias
  for (int i = t; i < 1024; i += 256) {
    int co = i >> 3, q4 = i & 7;
    float bias = bp[co];
    size_t base = (size_t)b*CC*NN + (size_t)co*NN + n0 + q4*4;
    float4 xv = *(const float4*)&x[base];
    float4 hv = *(float4*)&Ot[co*36 + q4*4];
    float4 o;
    o.x = xv.x + hv.x + bias;
    o.y = xv.y + hv.y + bias;
    o.z = xv.z + hv.z + bias;
    o.w = xv.w + hv.w + bias;
    *(float4*)&outp[base] = o;
  }
}

// ---------------------------------------------------------------------------
extern "C" void kernel_launch(void* const* d_in, const int* in_sizes, int n_in,
                              void* d_out, int out_size) {
  (void)in_sizes; (void)n_in; (void)out_size;
  const float* x    = (const float*)d_in[0];
  const float* gn_w = (const float*)d_in[1];
  const float* gn_b = (const float*)d_in[2];
  const float* wq   = (const float*)d_in[3];
  const float* bq   = (const float*)d_in[4];
  const float* wk   = (const float*)d_in[5];
  const float* bk   = (const float*)d_in[6];
  const float* wv   = (const float*)d_in[7];
  const float* bv   = (const float*)d_in[8];
  const float* wp   = (const float*)d_in[9];
  const float* bp   = (const float*)d_in[10];
  float* out = (float*)d_out;

  const int QKV_SMEM  = 99328;   // H 32K + W x2 64K + stats 1K
  const int ATTN_SMEM = 65536;
  const int PROJ_SMEM = 40960;
  cudaFuncSetAttribute(qkv_kernel,  cudaFuncAttributeMaxDynamicSharedMemorySize, QKV_SMEM);
  cudaFuncSetAttribute(attn_kernel, cudaFuncAttributeMaxDynamicSharedMemorySize, ATTN_SMEM);
  cudaFuncSetAttribute(proj_kernel, cudaFuncAttributeMaxDynamicSharedMemorySize, PROJ_SMEM);

  setup_kernel<<<288, 256>>>(x, wq, wk, wv, wp);
  qkv_kernel<<<64, 256, QKV_SMEM>>>(x, gn_w, gn_b, bq, bk, bv);
  attn_kernel<<<128, 256, ATTN_SMEM>>>();
  proj_kernel<<<256, 256, PROJ_SMEM>>>(x, bp, out);
}